// round 1
// baseline (speedup 1.0000x reference)
#include <cuda_runtime.h>
#include <math.h>
#include <stdint.h>

// ---------------- problem constants ----------------
#define BB   4
#define CDD  5
#define HIS  50
#define LL   20
#define TT   41
#define EE   300
#define HH   16
#define VV   16
#define RR   256
#define QQ   200
#define NSEQ 220      // 20 cdd seqs + 200 his seqs
#define NTOK 4401     // 4400 word tokens + 1 "ones" token (index 4400)
#define NPAIR 1000    // B*CDD*HIS

#define SCALE_INV 0.057735026918962574f   // 1/sqrt(300)

// ---------------- device scratch (no cudaMalloc allowed) ----------------
__device__ float g_word[NSEQ * LL * RR];     // word-attn output  [seq][t][r]
__device__ float g_q[HH * NTOK * RR];        // itrs q per head   [h][tok][r]
__device__ float g_v[NTOK * RR];             // itrs values       [tok][h*16+v]
__device__ float g_rep[NPAIR * RR];          // per-pair rep      [pair][r]

// =====================================================================
// K1: word-level MHSA. One block per (seq, head). 3520 blocks, 256 thr.
// =====================================================================
#define XP 301   // padded stride, gcd(301%32=13, 32)=1 -> conflict free
#define SMEM_WORD ((2 * LL * XP + LL * LL) * 4)

__global__ void __launch_bounds__(256) k_word(
    const int* __restrict__ cand, const int* __restrict__ clik,
    const float* __restrict__ emb,
    const float* __restrict__ Wq, const float* __restrict__ Wv)
{
    extern __shared__ float sm[];
    float* xs = sm;                 // [LL][XP]
    float* qs = sm + LL * XP;       // [LL][XP]  (reused as o)
    float* ss = sm + 2 * LL * XP;   // [LL][LL]
    __shared__ int toks[LL];

    const int seq = blockIdx.x >> 4;
    const int h   = blockIdx.x & 15;
    const int tid = threadIdx.x;

    if (tid < LL) {
        toks[tid] = (seq < 20) ? cand[seq * LL + tid]
                               : clik[(seq - 20) * LL + tid];
    }
    __syncthreads();

    // gather x = embedding[tokens]  [20,300]
    for (int i = tid; i < LL * EE; i += 256) {
        int t = i / EE, e = i - t * EE;
        xs[t * XP + e] = emb[toks[t] * EE + e];
    }
    __syncthreads();

    // q = x @ Wq[h]  — 2 columns per thread (150 active), 20 accumulators each
    if (tid < 150) {
        const int c0 = tid * 2, c1 = c0 + 1;
        float a0[LL], a1[LL];
#pragma unroll
        for (int t = 0; t < LL; t++) { a0[t] = 0.f; a1[t] = 0.f; }
        const float* W = Wq + h * EE * EE;
        for (int e = 0; e < EE; e++) {
            float w0 = W[e * EE + c0];
            float w1 = W[e * EE + c1];
#pragma unroll
            for (int t = 0; t < LL; t++) {
                float xv = xs[t * XP + e];
                a0[t] += xv * w0;
                a1[t] += xv * w1;
            }
        }
#pragma unroll
        for (int t = 0; t < LL; t++) {
            qs[t * XP + c0] = a0[t];
            qs[t * XP + c1] = a1[t];
        }
    }
    __syncthreads();

    // s = q @ x^T / sqrt(E)
    for (int i = tid; i < LL * LL; i += 256) {
        int t = i / LL, u = i - t * LL;
        float acc = 0.f;
        for (int e = 0; e < EE; e++) acc += qs[t * XP + e] * xs[u * XP + e];
        ss[i] = acc * SCALE_INV;
    }
    __syncthreads();

    // softmax rows
    if (tid < LL) {
        float m = -1e30f;
        for (int u = 0; u < LL; u++) m = fmaxf(m, ss[tid * LL + u]);
        float s = 0.f;
        for (int u = 0; u < LL; u++) {
            float ev = __expf(ss[tid * LL + u] - m);
            ss[tid * LL + u] = ev; s += ev;
        }
        float inv = 1.f / s;
        for (int u = 0; u < LL; u++) ss[tid * LL + u] *= inv;
    }
    __syncthreads();

    // o = a @ x  (overwrite qs)
    if (tid < 150) {
        const int c0 = tid * 2, c1 = c0 + 1;
        float a0[LL], a1[LL];
#pragma unroll
        for (int t = 0; t < LL; t++) { a0[t] = 0.f; a1[t] = 0.f; }
        for (int u = 0; u < LL; u++) {
            float x0 = xs[u * XP + c0], x1 = xs[u * XP + c1];
#pragma unroll
            for (int t = 0; t < LL; t++) {
                float av = ss[t * LL + u];
                a0[t] += av * x0;
                a1[t] += av * x1;
            }
        }
#pragma unroll
        for (int t = 0; t < LL; t++) {
            qs[t * XP + c0] = a0[t];
            qs[t * XP + c1] = a1[t];
        }
    }
    __syncthreads();

    // out = o @ Wv[h]  -> g_word[seq][t][h*16+v]
    const float* Wvh = Wv + h * EE * VV;
    for (int i = tid; i < LL * VV; i += 256) {
        int t = i / VV, v = i - (i / VV) * VV;
        float acc = 0.f;
        for (int e = 0; e < EE; e++) acc += qs[t * XP + e] * Wvh[e * VV + v];
        g_word[(seq * LL + t) * RR + h * VV + v] = acc;
    }
}

// =====================================================================
// K2: itrs q-projection + value-projection per head, token tiles of 32.
// grid = 16 * 138, block = 128 threads, 2 output columns per thread.
// =====================================================================
#define NT2 138   // ceil(4401/32)

__global__ void __launch_bounds__(128) k_proj(
    const float* __restrict__ Wq, const float* __restrict__ Wv)
{
    __shared__ float xs[32 * 257];
    const int h    = blockIdx.x / NT2;
    const int tile = blockIdx.x % NT2;
    const int tok0 = tile * 32;
    const int tid  = threadIdx.x;

    for (int i = tid; i < 32 * RR; i += 128) {
        int tt = i >> 8, r = i & 255;
        int tok = tok0 + tt;
        float v;
        if (tok < 4400)       v = g_word[tok * RR + r];
        else if (tok == 4400) v = 1.f;   // ones separator slot
        else                  v = 0.f;
        xs[tt * 257 + r] = v;
    }
    __syncthreads();

    // q = x @ Wq_itrs[h]: cols c0=tid, c1=tid+128; 32 accumulators each
    {
        const int c0 = tid, c1 = tid + 128;
        float a0[32], a1[32];
#pragma unroll
        for (int t = 0; t < 32; t++) { a0[t] = 0.f; a1[t] = 0.f; }
        const float* W = Wq + h * RR * RR;
        for (int e = 0; e < RR; e++) {
            float w0 = W[e * RR + c0];
            float w1 = W[e * RR + c1];
#pragma unroll
            for (int t = 0; t < 32; t++) {
                float xv = xs[t * 257 + e];
                a0[t] += xv * w0;
                a1[t] += xv * w1;
            }
        }
        float* qb = g_q + (h * NTOK + tok0) * RR;
#pragma unroll
        for (int t = 0; t < 32; t++) {
            if (tok0 + t < NTOK) {
                qb[t * RR + c0] = a0[t];
                qb[t * RR + c1] = a1[t];
            }
        }
    }

    // values: v[tok][h*16+v] = x_row @ Wv_itrs[h]
    const float* Wvh = Wv + h * RR * VV;
    for (int i = tid; i < 32 * VV; i += 128) {
        int tt = i >> 4, v = i & 15;
        int tok = tok0 + tt;
        if (tok < NTOK) {
            float acc = 0.f;
            for (int e = 0; e < RR; e++) acc += xs[tt * 257 + e] * Wvh[e * VV + v];
            g_v[tok * RR + h * VV + v] = acc;
        }
    }
}

// =====================================================================
// K3: per-pair fusion attention + additive pooling. 1000 blocks, 256 thr.
// =====================================================================
#define KP 257
#define PADROWS 44
#define SMEM_PAIR ((3 * PADROWS * KP + PADROWS * PADROWS + TT * VV + 96) * 4)

__global__ void __launch_bounds__(256) k_pair(
    const float* __restrict__ keyW, const float* __restrict__ keyb,
    const float* __restrict__ query)
{
    extern __shared__ float sm[];
    float* Ks   = sm;                       // keys   [44][KP] (rows >=41 zero)
    float* Qs   = Ks + PADROWS * KP;        // head q [44][KP]; later keyW stage
    float* Vals = Qs + PADROWS * KP;        // val    [44][KP]
    float* Ss   = Vals + PADROWS * KP;      // scores [44][44]; later lpart
    float* Vh   = Ss + PADROWS * PADROWS;   // values [41][16]
    float* Aux  = Vh + TT * VV;             // logits[48] + a2[48]

    const int p   = blockIdx.x;
    const int b   = p / (CDD * HIS);
    const int rem = p % (CDD * HIS);
    const int c   = rem / HIS;
    const int hh  = rem % HIS;
    const int cddTok0 = (b * CDD + c) * LL;
    const int hisTok0 = (20 + b * HIS + hh) * LL;
    const int tid = threadIdx.x;

    // keys: [cdd | ones | his], rows 41..43 zero-padded
    for (int i = tid; i < PADROWS * RR; i += 256) {
        int t = i >> 8, r = i & 255;
        float v = 0.f;
        if (t < 20)       v = g_word[(cddTok0 + t) * RR + r];
        else if (t == 20) v = 1.f;
        else if (t < TT)  v = g_word[(hisTok0 + t - 21) * RR + r];
        Ks[t * KP + r] = v;
    }
    // zero pad rows of Vals (rows 0..40 fully written by head loop)
    for (int i = tid; i < 3 * RR; i += 256) {
        int t = TT + i / RR, r = i % RR;
        Vals[t * KP + r] = 0.f;
    }
    __syncthreads();

    const int ti = tid / 11, ui = tid % 11;   // 121 active 4x4 score tiles
    const bool sact = (tid < 121);

    for (int h = 0; h < HH; h++) {
        // load per-head q rows and values
        for (int i = tid; i < PADROWS * RR; i += 256) {
            int t = i >> 8, r = i & 255;
            float v = 0.f;
            if (t < TT) {
                int tok = (t < 20) ? (cddTok0 + t)
                        : (t == 20) ? 4400 : (hisTok0 + t - 21);
                v = g_q[(h * NTOK + tok) * RR + r];
            }
            Qs[t * KP + r] = v;
        }
        for (int i = tid; i < TT * VV; i += 256) {
            int t = i / VV, v = i - (i / VV) * VV;
            int tok = (t < 20) ? (cddTok0 + t)
                    : (t == 20) ? 4400 : (hisTok0 + t - 21);
            Vh[t * VV + v] = g_v[tok * RR + h * VV + v];
        }
        __syncthreads();

        // S = Q @ K^T / sqrt(E), 4x4 register tiles
        if (sact) {
            const int t0 = ti * 4, u0 = ui * 4;
            float acc[4][4];
#pragma unroll
            for (int a = 0; a < 4; a++)
#pragma unroll
                for (int bq = 0; bq < 4; bq++) acc[a][bq] = 0.f;
            for (int r = 0; r < RR; r++) {
                float qv[4], kv[4];
#pragma unroll
                for (int a = 0; a < 4; a++) qv[a] = Qs[(t0 + a) * KP + r];
#pragma unroll
                for (int bq = 0; bq < 4; bq++) kv[bq] = Ks[(u0 + bq) * KP + r];
#pragma unroll
                for (int a = 0; a < 4; a++)
#pragma unroll
                    for (int bq = 0; bq < 4; bq++) acc[a][bq] += qv[a] * kv[bq];
            }
#pragma unroll
            for (int a = 0; a < 4; a++)
                if (t0 + a < TT)
#pragma unroll
                    for (int bq = 0; bq < 4; bq++)
                        if (u0 + bq < TT)
                            Ss[(t0 + a) * PADROWS + (u0 + bq)] = acc[a][bq] * SCALE_INV;
        }
        __syncthreads();

        // row softmax
        if (tid < TT) {
            float m = -1e30f;
            for (int u = 0; u < TT; u++) m = fmaxf(m, Ss[tid * PADROWS + u]);
            float s = 0.f;
            for (int u = 0; u < TT; u++) {
                float ev = __expf(Ss[tid * PADROWS + u] - m);
                Ss[tid * PADROWS + u] = ev; s += ev;
            }
            float inv = 1.f / s;
            for (int u = 0; u < TT; u++) Ss[tid * PADROWS + u] *= inv;
        }
        __syncthreads();

        // val slice: Vals[t][h*16+v] = A[t,:] @ Vh[:,v]
        for (int i = tid; i < TT * VV; i += 256) {
            int t = i / VV, v = i - (i / VV) * VV;
            float acc = 0.f;
            for (int u = 0; u < TT; u++) acc += Ss[t * PADROWS + u] * Vh[u * VV + v];
            Vals[t * KP + h * VV + v] = acc;
        }
        __syncthreads();
    }

    // ---- k = tanh(val @ keyW + b); logits = (k @ query)/sqrt(E) ----
    // tiles: 4 t-rows x 10 q-cols -> 11*20 = 220 tiles (tile id == tid)
    const int vti = tid / 20, vqi = tid % 20;
    const bool vact = (tid < 220);
    float kacc[4][10];
    if (vact) {
#pragma unroll
        for (int a = 0; a < 4; a++)
#pragma unroll
            for (int j = 0; j < 10; j++) kacc[a][j] = 0.f;
    }
    float* kw = Qs;   // reuse q buffer: 32*200 = 6400 floats
    for (int r0 = 0; r0 < RR; r0 += 32) {
        __syncthreads();
        for (int i = tid; i < 32 * QQ; i += 256) {
            int rr = i / QQ, q_ = i - (i / QQ) * QQ;
            kw[rr * QQ + q_] = keyW[(r0 + rr) * QQ + q_];
        }
        __syncthreads();
        if (vact) {
            const int t0 = vti * 4, q0 = vqi * 10;
            for (int rr = 0; rr < 32; rr++) {
                float vv[4];
#pragma unroll
                for (int a = 0; a < 4; a++) vv[a] = Vals[(t0 + a) * KP + r0 + rr];
#pragma unroll
                for (int j = 0; j < 10; j++) {
                    float w = kw[rr * QQ + q0 + j];
#pragma unroll
                    for (int a = 0; a < 4; a++) kacc[a][j] += vv[a] * w;
                }
            }
        }
    }
    __syncthreads();

    // tanh + partial logit contributions -> lpart (reuse Ss): [tile][4]
    if (vact) {
        const int q0 = vqi * 10;
#pragma unroll
        for (int a = 0; a < 4; a++) {
            float part = 0.f;
#pragma unroll
            for (int j = 0; j < 10; j++) {
                float kv = tanhf(kacc[a][j] + keyb[q0 + j]);
                part += kv * query[q0 + j];
            }
            Ss[tid * 4 + a] = part;
        }
    }
    __syncthreads();

    float* logits = Aux;
    float* a2     = Aux + 48;
    if (tid < TT) {
        int t0i = tid >> 2, sub = tid & 3;
        float s = 0.f;
        for (int qi = 0; qi < 20; qi++) s += Ss[(t0i * 20 + qi) * 4 + sub];
        logits[tid] = s * SCALE_INV;
    }
    __syncthreads();
    if (tid == 0) {
        float m = -1e30f;
        for (int t = 0; t < TT; t++) m = fmaxf(m, logits[t]);
        float s = 0.f;
        for (int t = 0; t < TT; t++) { float ev = __expf(logits[t] - m); a2[t] = ev; s += ev; }
        float inv = 1.f / s;
        for (int t = 0; t < TT; t++) a2[t] *= inv;
    }
    __syncthreads();

    // rep = a2 @ val
    if (tid < RR) {
        float acc = 0.f;
        for (int t = 0; t < TT; t++) acc += a2[t] * Vals[t * KP + tid];
        g_rep[p * RR + tid] = acc;
    }
}

// =====================================================================
// K4: mean over HIS, linear score, log_softmax over CDD. 1 block.
// =====================================================================
__global__ void __launch_bounds__(256) k_final(
    const float* __restrict__ ltr_w, const float* __restrict__ ltr_b,
    float* __restrict__ out)
{
    __shared__ float red[256];
    __shared__ float scores[BB * CDD];
    const int tid = threadIdx.x;

    for (int pair = 0; pair < BB * CDD; pair++) {
        float s = 0.f;
        for (int hh = 0; hh < HIS; hh++)
            s += g_rep[(pair * HIS + hh) * RR + tid];
        s *= (1.f / HIS);
        red[tid] = s * ltr_w[tid];
        __syncthreads();
        for (int st = 128; st > 0; st >>= 1) {
            if (tid < st) red[tid] += red[tid + st];
            __syncthreads();
        }
        if (tid == 0) scores[pair] = red[0] + ltr_b[0];
        __syncthreads();
    }
    if (tid < BB) {
        const int b = tid;
        float m = -1e30f;
        for (int cc = 0; cc < CDD; cc++) m = fmaxf(m, scores[b * CDD + cc]);
        float s = 0.f;
        for (int cc = 0; cc < CDD; cc++) s += __expf(scores[b * CDD + cc] - m);
        float lse = m + logf(s);
        for (int cc = 0; cc < CDD; cc++) out[b * CDD + cc] = scores[b * CDD + cc] - lse;
    }
}

// =====================================================================
// launch
// =====================================================================
extern "C" void kernel_launch(void* const* d_in, const int* in_sizes, int n_in,
                              void* d_out, int out_size)
{
    const int*   cand  = (const int*)d_in[0];
    const int*   clik  = (const int*)d_in[1];
    const float* emb   = (const float*)d_in[2];
    const float* Wq_w  = (const float*)d_in[3];
    const float* Wv_w  = (const float*)d_in[4];
    const float* Wq_i  = (const float*)d_in[5];
    const float* Wv_i  = (const float*)d_in[6];
    const float* keyW  = (const float*)d_in[7];
    const float* keyb  = (const float*)d_in[8];
    const float* query = (const float*)d_in[9];
    const float* ltr_w = (const float*)d_in[10];
    const float* ltr_b = (const float*)d_in[11];
    float* out = (float*)d_out;

    // idempotent, called every launch (no static guards)
    cudaFuncSetAttribute(k_word, cudaFuncAttributeMaxDynamicSharedMemorySize, SMEM_WORD);
    cudaFuncSetAttribute(k_pair, cudaFuncAttributeMaxDynamicSharedMemorySize, SMEM_PAIR);

    k_word<<<NSEQ * HH, 256, SMEM_WORD>>>(cand, clik, emb, Wq_w, Wv_w);
    k_proj<<<HH * NT2, 128>>>(Wq_i, Wv_i);
    k_pair<<<NPAIR, 256, SMEM_PAIR>>>(keyW, keyb, query);
    k_final<<<1, 256>>>(ltr_w, ltr_b, out);
}

// round 4
// speedup vs baseline: 1.3400x; 1.3400x over previous
#include <cuda_runtime.h>
#include <cuda_fp16.h>
#include <math.h>
#include <stdint.h>

// ---------------- problem constants ----------------
#define BB   4
#define CDD  5
#define HIS  50
#define LL   20
#define TT   41
#define EE   300
#define HH   16
#define VV   16
#define RR   256
#define QQ   200
#define NTOKW 4400      // word tokens (400 cdd + 4000 his)
#define NTOKP 4416      // padded itrs token rows (4401 real: +ones)
#define NPAIR 1000
#define HG   2          // heads per group
#define NGRP (HH / HG)

#define SCALE_INV 0.057735026918962574f   // 1/sqrt(300)

// ---------------- single pooled scratch (52.5 MB total) ----------------
// byte offsets (all 16B-aligned)
#define OFF_WORD   0u                       // float [4400][256]        4,505,600 B
#define OFF_V      4505600u                 // float [4416][256]        4,521,984 B
#define OFF_AUX    9027584u                 // float [4416][32]           565,248 B
#define OFF_WAUX   9592832u                 // float [256][32]             32,768 B
#define OFF_SDIAG  9625600u                 // float [220][16][400]     5,632,000 B
#define OFF_REP    15257600u                // float [1000][256]        1,024,000 B
#define OFF_SCR    16281600u                // float qw:2*4400*300 / qi:2*4416*256  10,560,000 B
#define OFF_C1     26841600u                // half  [4*16][100][1000] 12,800,000 B
#define OFF_C2     39641600u                // half  [4*16][1000][100] 12,800,000 B
#define OFF_XV     OFF_C1                   // float [4400][256] overlay (word phase only)
#define OFF_TOK    52441600u                // int   [4400]                17,600 B
#define POOL_BYTES 52459200u

__device__ __align__(16) unsigned char g_pool[POOL_BYTES];

#define P_WORD  ((float*)(g_pool + OFF_WORD))
#define P_V     ((float*)(g_pool + OFF_V))
#define P_AUX   ((float*)(g_pool + OFF_AUX))
#define P_WAUX  ((float*)(g_pool + OFF_WAUX))
#define P_SDIAG ((float*)(g_pool + OFF_SDIAG))
#define P_REP   ((float*)(g_pool + OFF_REP))
#define P_SCR   ((float*)(g_pool + OFF_SCR))
#define P_C1    ((__half*)(g_pool + OFF_C1))
#define P_C2    ((__half*)(g_pool + OFF_C2))
#define P_XV    ((float*)(g_pool + OFF_XV))
#define P_TOK   ((int*)(g_pool + OFF_TOK))

// =====================================================================
// K-tok: token id table
// =====================================================================
__global__ void __launch_bounds__(256) k_tok(
    const int* __restrict__ cand, const int* __restrict__ clik)
{
    int i = blockIdx.x * 256 + threadIdx.x;
    if (i < NTOKW) P_TOK[i] = (i < 400) ? cand[i] : clik[i - 400];
}

// =====================================================================
// K-aux: colsum/rowsum of Wq_itrs per head
// =====================================================================
__global__ void __launch_bounds__(256) k_w1aux(const float* __restrict__ Wq)
{
    int h = blockIdx.x;
    int k = threadIdx.x;
    const float* W = Wq + h * RR * RR;
    float cs = 0.f, rs = 0.f;
    for (int e = 0; e < RR; e++) cs += W[e * RR + k];
    for (int c = 0; c < RR; c++) rs += W[k * RR + c];
    P_WAUX[k * 32 + 2 * h]     = cs;
    P_WAUX[k * 32 + 2 * h + 1] = rs;
}

// =====================================================================
// SGEMMs: BM=128, BN=64, 256 threads, 8x4 microtile
// =====================================================================

// qw group: SCR[hl] = emb[tok][300] @ Wq_words[hg+hl][300,300]. BK=12.
__global__ void __launch_bounds__(256) k_gemm_qw(
    const float* __restrict__ emb, const float* __restrict__ W, int hg)
{
    __shared__ float As[12 * 132];
    __shared__ float Bs[12 * 64];
    __shared__ int stok[128];
    const int hl = blockIdx.z;
    const int m_base = blockIdx.y * 128;
    const int n_base = blockIdx.x * 64;
    const float* B = W + (hg + hl) * EE * EE;
    const int tid = threadIdx.x;
    const int ty = tid >> 4, tx = tid & 15;
    if (tid < 128) {
        int m = m_base + tid;
        stok[tid] = (m < NTOKW) ? P_TOK[m] : 0;
    }
    __syncthreads();
    float acc[8][4] = {};
    for (int k0 = 0; k0 < EE; k0 += 12) {
#pragma unroll
        for (int i = 0; i < 6; i++) {
            int id = tid + i * 256;
            int r = id / 12, c = id - r * 12;
            int m = m_base + r;
            As[c * 132 + r] = (m < NTOKW) ? emb[(size_t)stok[r] * EE + k0 + c] : 0.f;
        }
#pragma unroll
        for (int i = 0; i < 3; i++) {
            int id = tid + i * 256;
            int kk = id >> 6, n = id & 63;
            int nn = n_base + n;
            Bs[kk * 64 + n] = (nn < EE) ? B[(k0 + kk) * EE + nn] : 0.f;
        }
        __syncthreads();
#pragma unroll
        for (int kk = 0; kk < 12; kk++) {
            float4 a0 = *(float4*)(As + kk * 132 + ty * 8);
            float4 a1 = *(float4*)(As + kk * 132 + ty * 8 + 4);
            float4 bv = *(float4*)(Bs + kk * 64 + tx * 4);
            float av[8] = {a0.x,a0.y,a0.z,a0.w,a1.x,a1.y,a1.z,a1.w};
            float bw[4] = {bv.x,bv.y,bv.z,bv.w};
#pragma unroll
            for (int i = 0; i < 8; i++)
#pragma unroll
                for (int j = 0; j < 4; j++) acc[i][j] += av[i] * bw[j];
        }
        __syncthreads();
    }
    float* C = P_SCR + hl * NTOKW * EE;
#pragma unroll
    for (int i = 0; i < 8; i++) {
        int m = m_base + ty * 8 + i;
        if (m < NTOKW)
#pragma unroll
            for (int j = 0; j < 4; j++) {
                int n = n_base + tx * 4 + j;
                if (n < EE) C[m * EE + n] = acc[i][j];
            }
    }
}

// xv = emb[tok][300] @ Wv_words(all heads)[300,256]. BK=12.
__global__ void __launch_bounds__(256) k_gemm_xv(
    const float* __restrict__ emb, const float* __restrict__ Wv)
{
    __shared__ float As[12 * 132];
    __shared__ float Bs[12 * 64];
    __shared__ int stok[128];
    const int m_base = blockIdx.y * 128;
    const int n_base = blockIdx.x * 64;
    const int tid = threadIdx.x;
    const int ty = tid >> 4, tx = tid & 15;
    if (tid < 128) {
        int m = m_base + tid;
        stok[tid] = (m < NTOKW) ? P_TOK[m] : 0;
    }
    __syncthreads();
    float acc[8][4] = {};
    for (int k0 = 0; k0 < EE; k0 += 12) {
#pragma unroll
        for (int i = 0; i < 6; i++) {
            int id = tid + i * 256;
            int r = id / 12, c = id - r * 12;
            int m = m_base + r;
            As[c * 132 + r] = (m < NTOKW) ? emb[(size_t)stok[r] * EE + k0 + c] : 0.f;
        }
#pragma unroll
        for (int i = 0; i < 3; i++) {
            int id = tid + i * 256;
            int kk = id >> 6, n = id & 63;
            int j = n_base + n;
            Bs[kk * 64 + n] = Wv[(j >> 4) * (EE * VV) + (k0 + kk) * VV + (j & 15)];
        }
        __syncthreads();
#pragma unroll
        for (int kk = 0; kk < 12; kk++) {
            float4 a0 = *(float4*)(As + kk * 132 + ty * 8);
            float4 a1 = *(float4*)(As + kk * 132 + ty * 8 + 4);
            float4 bv = *(float4*)(Bs + kk * 64 + tx * 4);
            float av[8] = {a0.x,a0.y,a0.z,a0.w,a1.x,a1.y,a1.z,a1.w};
            float bw[4] = {bv.x,bv.y,bv.z,bv.w};
#pragma unroll
            for (int i = 0; i < 8; i++)
#pragma unroll
                for (int j = 0; j < 4; j++) acc[i][j] += av[i] * bw[j];
        }
        __syncthreads();
    }
#pragma unroll
    for (int i = 0; i < 8; i++) {
        int m = m_base + ty * 8 + i;
        if (m < NTOKW)
#pragma unroll
            for (int j = 0; j < 4; j++)
                P_XV[m * RR + n_base + tx * 4 + j] = acc[i][j];
    }
}

// itrs A-row: X2[m] = m<4400 ? word[m] : (m==4400 ? 1 : 0)
__device__ __forceinline__ float x2_elem(int m, int k) {
    if (m < NTOKW) return P_WORD[m * RR + k];
    return (m == NTOKW) ? 1.f : 0.f;
}

// qi group: SCR[hl] = X2[4416,256] @ Wq_itrs[hg+hl][256,256]. BK=16.
__global__ void __launch_bounds__(256) k_gemm_qi(const float* __restrict__ Wq, int hg)
{
    __shared__ float As[16 * 132];
    __shared__ float Bs[16 * 64];
    const int hl = blockIdx.z;
    const int m_base = blockIdx.y * 128;
    const int n_base = blockIdx.x * 64;
    const float* B = Wq + (hg + hl) * RR * RR;
    const int tid = threadIdx.x;
    const int ty = tid >> 4, tx = tid & 15;
    float acc[8][4] = {};
    for (int k0 = 0; k0 < RR; k0 += 16) {
#pragma unroll
        for (int i = 0; i < 8; i++) {
            int id = tid + i * 256;
            int r = id >> 4, c = id & 15;
            As[c * 132 + r] = x2_elem(m_base + r, k0 + c);
        }
#pragma unroll
        for (int i = 0; i < 4; i++) {
            int id = tid + i * 256;
            int kk = id >> 6, n = id & 63;
            Bs[kk * 64 + n] = B[(k0 + kk) * RR + n_base + n];
        }
        __syncthreads();
#pragma unroll
        for (int kk = 0; kk < 16; kk++) {
            float4 a0 = *(float4*)(As + kk * 132 + ty * 8);
            float4 a1 = *(float4*)(As + kk * 132 + ty * 8 + 4);
            float4 bv = *(float4*)(Bs + kk * 64 + tx * 4);
            float av[8] = {a0.x,a0.y,a0.z,a0.w,a1.x,a1.y,a1.z,a1.w};
            float bw[4] = {bv.x,bv.y,bv.z,bv.w};
#pragma unroll
            for (int i = 0; i < 8; i++)
#pragma unroll
                for (int j = 0; j < 4; j++) acc[i][j] += av[i] * bw[j];
        }
        __syncthreads();
    }
    float* C = P_SCR + hl * NTOKP * RR;
#pragma unroll
    for (int i = 0; i < 8; i++) {
        int m = m_base + ty * 8 + i;
        if (m < NTOKP)
#pragma unroll
            for (int j = 0; j < 4; j++)
                C[m * RR + n_base + tx * 4 + j] = acc[i][j];
    }
}

// v_itrs + aux = X2[4416,256] @ [Wv_itrs(all h) | Waux] (N=288). BK=16.
__global__ void __launch_bounds__(256) k_gemm_vi(const float* __restrict__ Wv)
{
    __shared__ float As[16 * 132];
    __shared__ float Bs[16 * 64];
    const int m_base = blockIdx.y * 128;
    const int n_base = blockIdx.x * 64;
    const int tid = threadIdx.x;
    const int ty = tid >> 4, tx = tid & 15;
    float acc[8][4] = {};
    for (int k0 = 0; k0 < RR; k0 += 16) {
#pragma unroll
        for (int i = 0; i < 8; i++) {
            int id = tid + i * 256;
            int r = id >> 4, c = id & 15;
            As[c * 132 + r] = x2_elem(m_base + r, k0 + c);
        }
#pragma unroll
        for (int i = 0; i < 4; i++) {
            int id = tid + i * 256;
            int kk = id >> 6, n = id & 63;
            int j = n_base + n;
            float v;
            if (j < RR) v = Wv[(j >> 4) * (RR * VV) + (k0 + kk) * VV + (j & 15)];
            else        v = P_WAUX[(k0 + kk) * 32 + (j - RR)];
            Bs[kk * 64 + n] = v;
        }
        __syncthreads();
#pragma unroll
        for (int kk = 0; kk < 16; kk++) {
            float4 a0 = *(float4*)(As + kk * 132 + ty * 8);
            float4 a1 = *(float4*)(As + kk * 132 + ty * 8 + 4);
            float4 bv = *(float4*)(Bs + kk * 64 + tx * 4);
            float av[8] = {a0.x,a0.y,a0.z,a0.w,a1.x,a1.y,a1.z,a1.w};
            float bw[4] = {bv.x,bv.y,bv.z,bv.w};
#pragma unroll
            for (int i = 0; i < 8; i++)
#pragma unroll
                for (int j = 0; j < 4; j++) acc[i][j] += av[i] * bw[j];
        }
        __syncthreads();
    }
#pragma unroll
    for (int i = 0; i < 8; i++) {
        int m = m_base + ty * 8 + i;
        if (m < NTOKP)
#pragma unroll
            for (int j = 0; j < 4; j++) {
                int n = n_base + tx * 4 + j;
                if (n < RR) P_V[m * RR + n] = acc[i][j];
                else        P_AUX[m * 32 + (n - RR)] = acc[i][j];
            }
    }
}

// NT cross GEMM (head group): C = qi[M,256] @ word[N,256]^T, fp16 out.
// sel: 0 -> C1 (cdd x his), 1 -> C2 (his x cdd). z = b*HG + hl.
__global__ void __launch_bounds__(256) k_cross(int hg, int sel)
{
    __shared__ float As[16 * 132];
    __shared__ float Bs[16 * 68];
    const int z = blockIdx.z;
    const int b = z / HG, hl = z - b * HG;
    const int M = sel ? 1000 : 100;
    const int N = sel ? 100 : 1000;
    const int aRowOff = sel ? 400 : 0;
    const int aRowsPerB = sel ? 1000 : 100;
    const int bRowOff = sel ? 0 : 400;
    const int bRowsPerB = sel ? 100 : 1000;
    const float* A = P_SCR + (size_t)(hl * NTOKP + aRowOff + b * aRowsPerB) * RR;
    const float* B = P_WORD + (size_t)(bRowOff + b * bRowsPerB) * RR;
    __half* C = (sel ? P_C2 : P_C1) + (size_t)(b * HH + hg + hl) * 100000;
    const int m_base = blockIdx.y * 128;
    const int n_base = blockIdx.x * 64;
    const int tid = threadIdx.x;
    const int ty = tid >> 4, tx = tid & 15;
    float acc[8][4] = {};
    for (int k0 = 0; k0 < RR; k0 += 16) {
#pragma unroll
        for (int i = 0; i < 8; i++) {
            int id = tid + i * 256;
            int r = id >> 4, c = id & 15;
            int m = m_base + r;
            As[c * 132 + r] = (m < M) ? A[m * RR + k0 + c] : 0.f;
        }
#pragma unroll
        for (int i = 0; i < 4; i++) {
            int id = tid + i * 256;
            int r = id >> 4, c = id & 15;
            int n = n_base + r;
            Bs[c * 68 + r] = (n < N) ? B[n * RR + k0 + c] : 0.f;
        }
        __syncthreads();
#pragma unroll
        for (int kk = 0; kk < 16; kk++) {
            float4 a0 = *(float4*)(As + kk * 132 + ty * 8);
            float4 a1 = *(float4*)(As + kk * 132 + ty * 8 + 4);
            float4 bv = *(float4*)(Bs + kk * 68 + tx * 4);
            float av[8] = {a0.x,a0.y,a0.z,a0.w,a1.x,a1.y,a1.z,a1.w};
            float bw[4] = {bv.x,bv.y,bv.z,bv.w};
#pragma unroll
            for (int i = 0; i < 8; i++)
#pragma unroll
                for (int j = 0; j < 4; j++) acc[i][j] += av[i] * bw[j];
        }
        __syncthreads();
    }
#pragma unroll
    for (int i = 0; i < 8; i++) {
        int m = m_base + ty * 8 + i;
        if (m < M)
#pragma unroll
            for (int j = 0; j < 4; j++) {
                int n = n_base + tx * 4 + j;
                if (n < N) C[m * N + n] = __float2half(acc[i][j]);
            }
    }
}

// =====================================================================
// word attention per (local head, seq), head group hg
// =====================================================================
#define XP2 304
#define SMEM_WORD2 ((2 * LL * XP2 + LL * LL + LL * VV) * 4)

__global__ void __launch_bounds__(256) k_word2(const float* __restrict__ emb, int hg)
{
    extern __shared__ float sm[];
    float* qs = sm;                       // [20][304]
    float* xs = qs + LL * XP2;            // [20][304]
    float* ss = xs + LL * XP2;            // [20][20]
    float* xv = ss + LL * LL;             // [20][16]
    __shared__ int toks[LL];

    const int hl  = blockIdx.x;
    const int h   = hg + hl;
    const int seq = blockIdx.y;
    const int tok0 = seq * LL;
    const int tid = threadIdx.x;

    if (tid < LL) toks[tid] = P_TOK[tok0 + tid];
    __syncthreads();

    for (int i = tid; i < LL * EE; i += 256) {
        int t = i / EE, e = i - t * EE;
        qs[t * XP2 + e] = P_SCR[(hl * NTOKW + tok0 + t) * EE + e];
        xs[t * XP2 + e] = emb[(size_t)toks[t] * EE + e];
    }
    for (int i = tid; i < LL * VV; i += 256) {
        int t = i >> 4, v = i & 15;
        xv[i] = P_XV[(tok0 + t) * RR + h * VV + v];
    }
    __syncthreads();

    if (tid < 100) {
        const int t0 = (tid / 10) * 2, u0 = (tid % 10) * 2;
        float a00=0,a01=0,a10=0,a11=0;
        for (int r = 0; r < EE; r += 4) {
            float4 q0 = *(float4*)(qs + t0 * XP2 + r);
            float4 q1 = *(float4*)(qs + (t0+1) * XP2 + r);
            float4 x0 = *(float4*)(xs + u0 * XP2 + r);
            float4 x1 = *(float4*)(xs + (u0+1) * XP2 + r);
            a00 += q0.x*x0.x + q0.y*x0.y + q0.z*x0.z + q0.w*x0.w;
            a01 += q0.x*x1.x + q0.y*x1.y + q0.z*x1.z + q0.w*x1.w;
            a10 += q1.x*x0.x + q1.y*x0.y + q1.z*x0.z + q1.w*x0.w;
            a11 += q1.x*x1.x + q1.y*x1.y + q1.z*x1.z + q1.w*x1.w;
        }
        ss[t0 * LL + u0]       = a00 * SCALE_INV;
        ss[t0 * LL + u0 + 1]   = a01 * SCALE_INV;
        ss[(t0+1) * LL + u0]   = a10 * SCALE_INV;
        ss[(t0+1) * LL + u0+1] = a11 * SCALE_INV;
    }
    __syncthreads();

    if (tid < LL) {
        float m = -1e30f;
        for (int u = 0; u < LL; u++) m = fmaxf(m, ss[tid * LL + u]);
        float s = 0.f;
        for (int u = 0; u < LL; u++) {
            float ev = __expf(ss[tid * LL + u] - m);
            ss[tid * LL + u] = ev; s += ev;
        }
        float inv = 1.f / s;
        for (int u = 0; u < LL; u++) ss[tid * LL + u] *= inv;
    }
    __syncthreads();

    for (int i = tid; i < LL * VV; i += 256) {
        int t = i >> 4, v = i & 15;
        float acc = 0.f;
        for (int u = 0; u < LL; u++) acc += ss[t * LL + u] * xv[u * VV + v];
        P_WORD[(tok0 + t) * RR + h * VV + v] = acc;
    }
}

// =====================================================================
// diag scores: per (local head, seq): qi[20,256] . word[20,256]^T
// =====================================================================
__global__ void __launch_bounds__(128) k_diag(int hg)
{
    __shared__ float qs[LL * 260];
    __shared__ float xs[LL * 260];
    const int hl  = blockIdx.x;
    const int h   = hg + hl;
    const int seq = blockIdx.y;
    const int tok0 = seq * LL;
    const int tid = threadIdx.x;

    for (int i = tid; i < LL * RR; i += 128) {
        int t = i >> 8, r = i & 255;
        qs[t * 260 + r] = P_SCR[(hl * NTOKP + tok0 + t) * RR + r];
        xs[t * 260 + r] = P_WORD[(tok0 + t) * RR + r];
    }
    __syncthreads();

    if (tid < 100) {
        const int t0 = (tid / 10) * 2, u0 = (tid % 10) * 2;
        float a00=0,a01=0,a10=0,a11=0;
        for (int r = 0; r < RR; r += 4) {
            float4 q0 = *(float4*)(qs + t0 * 260 + r);
            float4 q1 = *(float4*)(qs + (t0+1) * 260 + r);
            float4 x0 = *(float4*)(xs + u0 * 260 + r);
            float4 x1 = *(float4*)(xs + (u0+1) * 260 + r);
            a00 += q0.x*x0.x + q0.y*x0.y + q0.z*x0.z + q0.w*x0.w;
            a01 += q0.x*x1.x + q0.y*x1.y + q0.z*x1.z + q0.w*x1.w;
            a10 += q1.x*x0.x + q1.y*x0.y + q1.z*x0.z + q1.w*x0.w;
            a11 += q1.x*x1.x + q1.y*x1.y + q1.z*x1.z + q1.w*x1.w;
        }
        float* D = P_SDIAG + (seq * HH + h) * (LL * LL);
        D[t0 * LL + u0]       = a00;
        D[t0 * LL + u0 + 1]   = a01;
        D[(t0+1) * LL + u0]   = a10;
        D[(t0+1) * LL + u0+1] = a11;
    }
}

// =====================================================================
// per-pair: assemble scores + softmax + A@V + keyW + pool
// =====================================================================
#define VSTR 260
#define SMEM_PAIR2 ((TT*44 + 44*VSTR + 44*VV + 16*QQ + QQ + QQ + 48 + 48) * 4)

__global__ void __launch_bounds__(256) k_pair2(
    const float* __restrict__ keyW, const float* __restrict__ keyb,
    const float* __restrict__ query)
{
    extern __shared__ float sm[];
    float* S    = sm;                    // [41][44]; later lpart(880)
    float* Vals = S + TT * 44;           // [44][260]
    float* Vh   = Vals + 44 * VSTR;      // [44][16]
    float* kwst = Vh + 44 * VV;          // [16][200]
    float* kb   = kwst + 16 * QQ;        // [200]
    float* qv   = kb + QQ;               // [200]
    float* logits = qv + QQ;             // [48]
    float* a2   = logits + 48;           // [48]

    const int p  = blockIdx.x;
    const int b  = p / (CDD * HIS);
    const int rem = p - b * (CDD * HIS);
    const int c  = rem / HIS;
    const int h2 = rem - c * HIS;
    const int cddSeq = b * CDD + c;            // 0..19
    const int hisSeq = 20 + b * HIS + h2;      // 20..219
    const int cddTok0 = cddSeq * LL;
    const int hisTok0 = hisSeq * LL;
    const int tid = threadIdx.x;

    for (int i = tid; i < QQ; i += 256) { kb[i] = keyb[i]; qv[i] = query[i]; }
    for (int i = tid; i < 3 * VSTR; i += 256) Vals[TT * VSTR + i] = 0.f;
    __syncthreads();

    for (int h = 0; h < HH; h++) {
        for (int i = tid; i < TT * TT; i += 256) {
            int t = i / TT, u = i - t * TT;
            float v;
            if (t < LL) {
                if (u < LL)
                    v = P_SDIAG[(cddSeq * HH + h) * 400 + t * LL + u];
                else if (u == LL)
                    v = P_AUX[(cddTok0 + t) * 32 + 2*h + 1];
                else
                    v = __half2float(P_C1[(size_t)(b * HH + h) * 100000
                                          + (c * LL + t) * 1000 + h2 * LL + (u - 21)]);
            } else if (t == LL) {
                if (u < LL)       v = P_AUX[(cddTok0 + u) * 32 + 2*h];
                else if (u == LL) v = P_AUX[NTOKW * 32 + 2*h];
                else              v = P_AUX[(hisTok0 + u - 21) * 32 + 2*h];
            } else {
                int tt = t - 21;
                if (u < LL)
                    v = __half2float(P_C2[(size_t)(b * HH + h) * 100000
                                          + (h2 * LL + tt) * 100 + c * LL + u]);
                else if (u == LL)
                    v = P_AUX[(hisTok0 + tt) * 32 + 2*h + 1];
                else
                    v = P_SDIAG[(hisSeq * HH + h) * 400 + tt * LL + (u - 21)];
            }
            S[t * 44 + u] = v * SCALE_INV;
        }
        for (int i = tid; i < TT * VV; i += 256) {
            int t = i >> 4, v = i & 15;
            int tok = (t < LL) ? (cddTok0 + t) : (t == LL) ? NTOKW : (hisTok0 + t - 21);
            Vh[t * VV + v] = P_V[tok * RR + h * VV + v];
        }
        __syncthreads();

        if (tid < TT) {
            float m = -1e30f;
            for (int u = 0; u < TT; u++) m = fmaxf(m, S[tid * 44 + u]);
            float s = 0.f;
            for (int u = 0; u < TT; u++) {
                float ev = __expf(S[tid * 44 + u] - m);
                S[tid * 44 + u] = ev; s += ev;
            }
            float inv = 1.f / s;
            for (int u = 0; u < TT; u++) S[tid * 44 + u] *= inv;
        }
        __syncthreads();

        for (int i = tid; i < TT * VV; i += 256) {
            int t = i >> 4, v = i & 15;
            float acc = 0.f;
            for (int u = 0; u < TT; u++) acc += S[t * 44 + u] * Vh[u * VV + v];
            Vals[t * VSTR + h * VV + v] = acc;
        }
        __syncthreads();
    }

    // k = tanh(val @ keyW + b); logits = (k @ query)/sqrt(E)
    const int vti = tid / 20, vqi = tid % 20;
    const bool vact = (tid < 220);
    float kacc[4][10];
    if (vact)
#pragma unroll
        for (int a = 0; a < 4; a++)
#pragma unroll
            for (int j = 0; j < 10; j++) kacc[a][j] = 0.f;

    for (int r0 = 0; r0 < RR; r0 += 16) {
        __syncthreads();
        for (int i = tid; i < 16 * QQ; i += 256) {
            int rr = i / QQ, q_ = i - rr * QQ;
            kwst[rr * QQ + q_] = keyW[(r0 + rr) * QQ + q_];
        }
        __syncthreads();
        if (vact) {
            const int t0 = vti * 4, q0 = vqi * 10;
            for (int rr = 0; rr < 16; rr++) {
                float vv[4];
#pragma unroll
                for (int a = 0; a < 4; a++) vv[a] = Vals[(t0 + a) * VSTR + r0 + rr];
#pragma unroll
                for (int j = 0; j < 10; j++) {
                    float w = kwst[rr * QQ + q0 + j];
#pragma unroll
                    for (int a = 0; a < 4; a++) kacc[a][j] += vv[a] * w;
                }
            }
        }
    }
    __syncthreads();

    if (vact) {
        const int q0 = vqi * 10;
#pragma unroll
        for (int a = 0; a < 4; a++) {
            float part = 0.f;
#pragma unroll
            for (int j = 0; j < 10; j++) {
                float kv = tanhf(kacc[a][j] + kb[q0 + j]);
                part += kv * qv[q0 + j];
            }
            S[tid * 4 + a] = part;
        }
    }
    __syncthreads();

    if (tid < TT) {
        int t0i = tid >> 2, sub = tid & 3;
        float s = 0.f;
        for (int qi = 0; qi < 20; qi++) s += S[(t0i * 20 + qi) * 4 + sub];
        logits[tid] = s * SCALE_INV;
    }
    __syncthreads();
    if (tid == 0) {
        float m = -1e30f;
        for (int t = 0; t < TT; t++) m = fmaxf(m, logits[t]);
        float s = 0.f;
        for (int t = 0; t < TT; t++) { float ev = __expf(logits[t] - m); a2[t] = ev; s += ev; }
        float inv = 1.f / s;
        for (int t = 0; t < TT; t++) a2[t] *= inv;
    }
    __syncthreads();

    if (tid < RR) {
        float acc = 0.f;
        for (int t = 0; t < TT; t++) acc += a2[t] * Vals[t * VSTR + tid];
        P_REP[p * RR + tid] = acc;
    }
}

// =====================================================================
// final: mean over HIS, score, log_softmax per batch
// =====================================================================
__global__ void __launch_bounds__(256) k_final(
    const float* __restrict__ ltr_w, const float* __restrict__ ltr_b,
    float* __restrict__ out)
{
    __shared__ float red[256];
    __shared__ float sc[CDD];
    const int b = blockIdx.x;
    const int tid = threadIdx.x;

    for (int c = 0; c < CDD; c++) {
        float s = 0.f;
        const int base = ((b * CDD + c) * HIS) * RR + tid;
        for (int hh = 0; hh < HIS; hh++) s += P_REP[base + hh * RR];
        red[tid] = s * (1.f / HIS) * ltr_w[tid];
        __syncthreads();
        for (int st = 128; st > 0; st >>= 1) {
            if (tid < st) red[tid] += red[tid + st];
            __syncthreads();
        }
        if (tid == 0) sc[c] = red[0] + ltr_b[0];
        __syncthreads();
    }
    if (tid == 0) {
        float m = -1e30f;
        for (int c = 0; c < CDD; c++) m = fmaxf(m, sc[c]);
        float s = 0.f;
        for (int c = 0; c < CDD; c++) s += __expf(sc[c] - m);
        float lse = m + logf(s);
        for (int c = 0; c < CDD; c++) out[b * CDD + c] = sc[c] - lse;
    }
}

// =====================================================================
// launch
// =====================================================================
extern "C" void kernel_launch(void* const* d_in, const int* in_sizes, int n_in,
                              void* d_out, int out_size)
{
    const int*   cand  = (const int*)d_in[0];
    const int*   clik  = (const int*)d_in[1];
    const float* emb   = (const float*)d_in[2];
    const float* Wq_w  = (const float*)d_in[3];
    const float* Wv_w  = (const float*)d_in[4];
    const float* Wq_i  = (const float*)d_in[5];
    const float* Wv_i  = (const float*)d_in[6];
    const float* keyW  = (const float*)d_in[7];
    const float* keyb  = (const float*)d_in[8];
    const float* query = (const float*)d_in[9];
    const float* ltr_w = (const float*)d_in[10];
    const float* ltr_b = (const float*)d_in[11];
    float* out = (float*)d_out;

    cudaFuncSetAttribute(k_word2, cudaFuncAttributeMaxDynamicSharedMemorySize, SMEM_WORD2);
    cudaFuncSetAttribute(k_pair2, cudaFuncAttributeMaxDynamicSharedMemorySize, SMEM_PAIR2);

    k_tok<<<(NTOKW + 255) / 256, 256>>>(cand, clik);
    k_w1aux<<<HH, 256>>>(Wq_i);
    k_gemm_xv<<<dim3(4, 35), 256>>>(emb, Wv_w);

    // word stage: 2-head groups through shared scratch
    for (int g = 0; g < NGRP; g++) {
        k_gemm_qw<<<dim3(5, 35, HG), 256>>>(emb, Wq_w, g * HG);
        k_word2<<<dim3(HG, 220), 256, SMEM_WORD2>>>(emb, g * HG);
    }

    k_gemm_vi<<<dim3(5, 35), 256>>>(Wv_i);

    // itrs stage: 2-head groups through shared scratch
    for (int g = 0; g < NGRP; g++) {
        k_gemm_qi<<<dim3(4, 35, HG), 256>>>(Wq_i, g * HG);
        k_diag<<<dim3(HG, 220), 128>>>(g * HG);
        k_cross<<<dim3(16, 1, BB * HG), 256>>>(g * HG, 0);  // C1: cdd x his
        k_cross<<<dim3(2, 8, BB * HG), 256>>>(g * HG, 1);   // C2: his x cdd
    }

    k_pair2<<<NPAIR, 256, SMEM_PAIR2>>>(keyW, keyb, query);
    k_final<<<BB, 256>>>(ltr_w, ltr_b, out);
}

// round 7
// speedup vs baseline: 2.3880x; 1.7821x over previous
#include <cuda_runtime.h>
#include <cuda_fp16.h>
#include <math.h>
#include <stdint.h>

// ---------------- problem constants ----------------
#define BB   4
#define CDD  5
#define HIS  50
#define LL   20
#define TT   41
#define EE   300
#define HH   16
#define VV   16
#define RR   256
#define QQ   200
#define NTOKW 4400
#define NTOKP 4416
#define NPAIR 1000
#define HG   4
#define NGRP (HH / HG)

#define SCALE_INV 0.057735026918962574f   // 1/sqrt(300)

// ---------------- pooled scratch (57.8 MiB) ----------------
#define OFF_WORD   0u            // float [4400][256]          4,505,600
#define OFF_V      4505600u      // float [4416][256]          4,521,984
#define OFF_AUX    9027584u      // float [4416][32]             565,248
#define OFF_WAUX   9592832u      // float [256][32]               32,768
#define OFF_SDIAG  9625600u      // float [220][16][400]       5,632,000
#define OFF_REP    15257600u     // float [1000][256]          1,024,000
#define OFF_SCR    16281600u     // half qw [4][4400][300] = 10,560,000 (qi needs 9,043,968)
#define OFF_C1     26841600u     // half [64][100][1000]      12,800,000
#define OFF_C2     39641600u     // half [64][1000][100]      12,800,000
#define OFF_EH16   52441600u     // half [4400][320]           2,816,000
#define OFF_WH16   55257600u     // half [4416][256]           2,260,992
#define OFF_WT     57518592u     // half W^T (max 16*300*320)  3,072,000
#define OFF_TOK    60590592u     // int [4400]                    17,600
#define OFF_XV     OFF_C1        // float [4400][256] overlay (word phase only)
#define POOL_BYTES 60608192u

__device__ __align__(16) unsigned char g_pool[POOL_BYTES];

#define P_WORD  ((float*)(g_pool + OFF_WORD))
#define P_V     ((float*)(g_pool + OFF_V))
#define P_AUX   ((float*)(g_pool + OFF_AUX))
#define P_WAUX  ((float*)(g_pool + OFF_WAUX))
#define P_SDIAG ((float*)(g_pool + OFF_SDIAG))
#define P_REP   ((float*)(g_pool + OFF_REP))
#define P_C1    ((__half*)(g_pool + OFF_C1))
#define P_C2    ((__half*)(g_pool + OFF_C2))
#define P_XV    ((float*)(g_pool + OFF_XV))
#define P_TOK   ((int*)(g_pool + OFF_TOK))
#define H_SCR   ((__half*)(g_pool + OFF_SCR))
#define H_EH16  ((__half*)(g_pool + OFF_EH16))
#define H_WH16  ((__half*)(g_pool + OFF_WH16))
#define H_WT    ((__half*)(g_pool + OFF_WT))

// =====================================================================
// small prep kernels
// =====================================================================
__global__ void __launch_bounds__(256) k_tok(const int* __restrict__ cand,
                                             const int* __restrict__ clik) {
    int i = blockIdx.x * 256 + threadIdx.x;
    if (i < NTOKW) P_TOK[i] = (i < 400) ? cand[i] : clik[i - 400];
}

__global__ void __launch_bounds__(256) k_w1aux(const float* __restrict__ Wq) {
    int h = blockIdx.x, k = threadIdx.x;
    const float* W = Wq + h * RR * RR;
    float cs = 0.f, rs = 0.f;
    for (int e = 0; e < RR; e++) cs += W[e * RR + k];
    for (int c = 0; c < RR; c++) rs += W[k * RR + c];
    P_WAUX[k * 32 + 2 * h] = cs;
    P_WAUX[k * 32 + 2 * h + 1] = rs;
}

__global__ void __launch_bounds__(256) k_embh16(const float* __restrict__ emb) {
    int i = blockIdx.x * 256 + threadIdx.x;
    if (i < NTOKW * 320) {
        int row = i / 320, e = i - row * 320;
        __half v = __float2half(0.f);
        if (e < EE) v = __float2half(emb[(size_t)P_TOK[row] * EE + e]);
        H_EH16[i] = v;
    }
}

__global__ void __launch_bounds__(256) k_wordh16() {
    int i = blockIdx.x * 256 + threadIdx.x;
    if (i < NTOKP * RR) {
        int row = i >> 8;
        float v = 0.f;
        if (row < NTOKW) v = P_WORD[i];
        else if (row == NTOKW) v = 1.f;
        H_WH16[i] = __float2half(v);
    }
}

// W^T fp16: WT[h][n][k] = W[h][k][n]  (k padded to kp with zeros)
__global__ void __launch_bounds__(256) k_wT(const float* __restrict__ W,
                                            int kdim, int ndim, int kp) {
    int i = blockIdx.x * 256 + threadIdx.x;
    int per_h = ndim * kp;
    if (i < HH * per_h) {
        int h = i / per_h, rem = i - h * per_h;
        int n = rem / kp, k = rem - n * kp;
        __half v = __float2half(0.f);
        if (k < kdim) v = __float2half(W[(size_t)h * kdim * ndim + (size_t)k * ndim + n]);
        H_WT[i] = v;
    }
}

// =====================================================================
// HMMA GEMM via mma.sync m16n8k16: C_half[M,N] = A_h16[M,K] @ B_h16[N,K]^T
// block 128x64, 8 warps (4m x 2n), warp tile 32x32, BK=32.
// mode: 0=qw 1=qi 2=c1 3=c2
// =====================================================================
#define BKH 32
#define SPAD 40   // half stride (conflict-free for fragment loads)

__global__ void __launch_bounds__(256) k_mma(int mode, int hg) {
    __shared__ __half As[128 * SPAD];
    __shared__ __half Bs[64 * SPAD];

    const int tid = threadIdx.x;
    const int wid = tid >> 5, lane = tid & 31;
    const int wm = wid & 3, wn = wid >> 2;       // 4 m-warps x 2 n-warps
    const int g = lane >> 2, t2 = (lane & 3) * 2;
    const int z = blockIdx.z;

    int M, N, K, lda, ldb, ldc;
    const __half *A, *B;
    __half* Cp;
    if (mode == 0) {
        M = NTOKW; N = 300; K = 320; lda = 320; ldb = 320; ldc = 300;
        A = H_EH16; B = H_WT + (size_t)(hg + z) * 300 * 320;
        Cp = H_SCR + (size_t)z * NTOKW * 300;
    } else if (mode == 1) {
        M = NTOKP; N = 256; K = 256; lda = 256; ldb = 256; ldc = 256;
        A = H_WH16; B = H_WT + (size_t)(hg + z) * 256 * 256;
        Cp = H_SCR + (size_t)z * NTOKP * 256;
    } else if (mode == 2) {
        int b = z >> 2, hl = z & 3;
        M = 100; N = 1000; K = 256; lda = 256; ldb = 256; ldc = 1000;
        A = H_SCR + ((size_t)hl * NTOKP + b * 100) * 256;
        B = H_WH16 + (size_t)(400 + b * 1000) * 256;
        Cp = P_C1 + (size_t)(b * HH + hg + hl) * 100000;
    } else {
        int b = z >> 2, hl = z & 3;
        M = 1000; N = 100; K = 256; lda = 256; ldb = 256; ldc = 100;
        A = H_SCR + ((size_t)hl * NTOKP + 400 + b * 1000) * 256;
        B = H_WH16 + (size_t)(b * 100) * 256;
        Cp = P_C2 + (size_t)(b * HH + hg + hl) * 100000;
    }
    const int m_base = blockIdx.y * 128;
    const int n_base = blockIdx.x * 64;

    float acc[2][4][4];
#pragma unroll
    for (int i = 0; i < 2; i++)
#pragma unroll
        for (int j = 0; j < 4; j++)
#pragma unroll
            for (int q = 0; q < 4; q++) acc[i][j][q] = 0.f;

    for (int k0 = 0; k0 < K; k0 += BKH) {
        // A tile: 128 x 32 halves = 512 uint4 segments (2 per thread)
#pragma unroll
        for (int it = 0; it < 2; it++) {
            int idx = tid + it * 256;
            int r = idx >> 2, seg = idx & 3;
            uint4 v = make_uint4(0, 0, 0, 0);
            int m = m_base + r;
            if (m < M) v = *(const uint4*)(A + (size_t)m * lda + k0 + seg * 8);
            *(uint4*)(As + r * SPAD + seg * 8) = v;
        }
        // B tile: 64 x 32 halves = 256 uint4 (1 per thread)
        {
            int r = tid >> 2, seg = tid & 3;
            uint4 v = make_uint4(0, 0, 0, 0);
            int n = n_base + r;
            if (n < N) v = *(const uint4*)(B + (size_t)n * ldb + k0 + seg * 8);
            *(uint4*)(Bs + r * SPAD + seg * 8) = v;
        }
        __syncthreads();

#pragma unroll
        for (int ks = 0; ks < 2; ks++) {
            const int kb = ks * 16;
            uint32_t ra[2][4], rb[4][2];
#pragma unroll
            for (int i = 0; i < 2; i++) {
                const __half* ab = As + (wm * 32 + i * 16) * SPAD + kb;
                ra[i][0] = *(const uint32_t*)(ab + g * SPAD + t2);
                ra[i][1] = *(const uint32_t*)(ab + (g + 8) * SPAD + t2);
                ra[i][2] = *(const uint32_t*)(ab + g * SPAD + t2 + 8);
                ra[i][3] = *(const uint32_t*)(ab + (g + 8) * SPAD + t2 + 8);
            }
#pragma unroll
            for (int j = 0; j < 4; j++) {
                const __half* bb = Bs + (wn * 32 + j * 8 + g) * SPAD + kb;
                rb[j][0] = *(const uint32_t*)(bb + t2);
                rb[j][1] = *(const uint32_t*)(bb + t2 + 8);
            }
#pragma unroll
            for (int i = 0; i < 2; i++)
#pragma unroll
                for (int j = 0; j < 4; j++) {
                    asm volatile(
                        "mma.sync.aligned.m16n8k16.row.col.f32.f16.f16.f32 "
                        "{%0,%1,%2,%3}, {%4,%5,%6,%7}, {%8,%9}, {%0,%1,%2,%3};"
                        : "+f"(acc[i][j][0]), "+f"(acc[i][j][1]),
                          "+f"(acc[i][j][2]), "+f"(acc[i][j][3])
                        : "r"(ra[i][0]), "r"(ra[i][1]), "r"(ra[i][2]), "r"(ra[i][3]),
                          "r"(rb[j][0]), "r"(rb[j][1]));
                }
        }
        __syncthreads();
    }

    // epilogue: fp16 stores (half2 per row-pair of cols)
#pragma unroll
    for (int i = 0; i < 2; i++) {
        int r0 = m_base + wm * 32 + i * 16 + g;
        int r1 = r0 + 8;
#pragma unroll
        for (int j = 0; j < 4; j++) {
            int col = n_base + wn * 32 + j * 8 + t2;
            if (col < N) {
                __half2 v0 = __floats2half2_rn(acc[i][j][0], acc[i][j][1]);
                __half2 v1 = __floats2half2_rn(acc[i][j][2], acc[i][j][3]);
                if (r0 < M) *(__half2*)(Cp + (size_t)r0 * ldc + col) = v0;
                if (r1 < M) *(__half2*)(Cp + (size_t)r1 * ldc + col) = v1;
            }
        }
    }
}

// =====================================================================
// FFMA GEMMs kept: xv (X @ Wv_words, fp32) and vi (X2 @ [Wv_itrs|Waux])
// =====================================================================
__global__ void __launch_bounds__(256) k_gemm_xv(
    const float* __restrict__ emb, const float* __restrict__ Wv)
{
    __shared__ float As[12 * 132];
    __shared__ float Bs[12 * 64];
    __shared__ int stok[128];
    const int m_base = blockIdx.y * 128, n_base = blockIdx.x * 64;
    const int tid = threadIdx.x, ty = tid >> 4, tx = tid & 15;
    if (tid < 128) { int m = m_base + tid; stok[tid] = (m < NTOKW) ? P_TOK[m] : 0; }
    __syncthreads();
    float acc[8][4] = {};
    for (int k0 = 0; k0 < EE; k0 += 12) {
#pragma unroll
        for (int i = 0; i < 6; i++) {
            int id = tid + i * 256; int r = id / 12, c = id - r * 12;
            int m = m_base + r;
            As[c * 132 + r] = (m < NTOKW) ? emb[(size_t)stok[r] * EE + k0 + c] : 0.f;
        }
#pragma unroll
        for (int i = 0; i < 3; i++) {
            int id = tid + i * 256; int kk = id >> 6, n = id & 63;
            int j = n_base + n;
            Bs[kk * 64 + n] = Wv[(j >> 4) * (EE * VV) + (k0 + kk) * VV + (j & 15)];
        }
        __syncthreads();
#pragma unroll
        for (int kk = 0; kk < 12; kk++) {
            float4 a0 = *(float4*)(As + kk * 132 + ty * 8);
            float4 a1 = *(float4*)(As + kk * 132 + ty * 8 + 4);
            float4 bv = *(float4*)(Bs + kk * 64 + tx * 4);
            float av[8] = {a0.x,a0.y,a0.z,a0.w,a1.x,a1.y,a1.z,a1.w};
            float bw[4] = {bv.x,bv.y,bv.z,bv.w};
#pragma unroll
            for (int i = 0; i < 8; i++)
#pragma unroll
                for (int j = 0; j < 4; j++) acc[i][j] += av[i] * bw[j];
        }
        __syncthreads();
    }
#pragma unroll
    for (int i = 0; i < 8; i++) {
        int m = m_base + ty * 8 + i;
        if (m < NTOKW)
#pragma unroll
            for (int j = 0; j < 4; j++)
                P_XV[m * RR + n_base + tx * 4 + j] = acc[i][j];
    }
}

__device__ __forceinline__ float x2_elem(int m, int k) {
    if (m < NTOKW) return P_WORD[m * RR + k];
    return (m == NTOKW) ? 1.f : 0.f;
}

__global__ void __launch_bounds__(256) k_gemm_vi(const float* __restrict__ Wv)
{
    __shared__ float As[16 * 132];
    __shared__ float Bs[16 * 64];
    const int m_base = blockIdx.y * 128, n_base = blockIdx.x * 64;
    const int tid = threadIdx.x, ty = tid >> 4, tx = tid & 15;
    float acc[8][4] = {};
    for (int k0 = 0; k0 < RR; k0 += 16) {
#pragma unroll
        for (int i = 0; i < 8; i++) {
            int id = tid + i * 256; int r = id >> 4, c = id & 15;
            As[c * 132 + r] = x2_elem(m_base + r, k0 + c);
        }
#pragma unroll
        for (int i = 0; i < 4; i++) {
            int id = tid + i * 256; int kk = id >> 6, n = id & 63;
            int j = n_base + n;
            float v;
            if (j < RR) v = Wv[(j >> 4) * (RR * VV) + (k0 + kk) * VV + (j & 15)];
            else        v = P_WAUX[(k0 + kk) * 32 + (j - RR)];
            Bs[kk * 64 + n] = v;
        }
        __syncthreads();
#pragma unroll
        for (int kk = 0; kk < 16; kk++) {
            float4 a0 = *(float4*)(As + kk * 132 + ty * 8);
            float4 a1 = *(float4*)(As + kk * 132 + ty * 8 + 4);
            float4 bv = *(float4*)(Bs + kk * 64 + tx * 4);
            float av[8] = {a0.x,a0.y,a0.z,a0.w,a1.x,a1.y,a1.z,a1.w};
            float bw[4] = {bv.x,bv.y,bv.z,bv.w};
#pragma unroll
            for (int i = 0; i < 8; i++)
#pragma unroll
                for (int j = 0; j < 4; j++) acc[i][j] += av[i] * bw[j];
        }
        __syncthreads();
    }
#pragma unroll
    for (int i = 0; i < 8; i++) {
        int m = m_base + ty * 8 + i;
        if (m < NTOKP)
#pragma unroll
            for (int j = 0; j < 4; j++) {
                int n = n_base + tx * 4 + j;
                if (n < RR) P_V[m * RR + n] = acc[i][j];
                else        P_AUX[m * 32 + (n - RR)] = acc[i][j];
            }
    }
}

// =====================================================================
// word attention per (local head, seq); q from fp16 scr
// =====================================================================
#define XP2 304
#define SMEM_WORD2 ((2 * LL * XP2 + LL * LL + LL * VV) * 4)

__global__ void __launch_bounds__(256) k_word2(int hg)
{
    extern __shared__ float sm[];
    float* qs = sm;
    float* xs = qs + LL * XP2;
    float* ss = xs + LL * XP2;
    float* xv = ss + LL * LL;

    const int hl = blockIdx.x, h = hg + hl;
    const int seq = blockIdx.y, tok0 = seq * LL;
    const int tid = threadIdx.x;

    for (int i = tid; i < LL * EE; i += 256) {
        int t = i / EE, e = i - t * EE;
        qs[t * XP2 + e] = __half2float(H_SCR[((size_t)hl * NTOKW + tok0 + t) * 300 + e]);
        xs[t * XP2 + e] = __half2float(H_EH16[(size_t)(tok0 + t) * 320 + e]);
    }
    for (int i = tid; i < LL * VV; i += 256) {
        int t = i >> 4, v = i & 15;
        xv[i] = P_XV[(tok0 + t) * RR + h * VV + v];
    }
    __syncthreads();

    if (tid < 100) {
        const int t0 = (tid / 10) * 2, u0 = (tid % 10) * 2;
        float a00=0,a01=0,a10=0,a11=0;
        for (int r = 0; r < EE; r += 4) {
            float4 q0 = *(float4*)(qs + t0 * XP2 + r);
            float4 q1 = *(float4*)(qs + (t0+1) * XP2 + r);
            float4 x0 = *(float4*)(xs + u0 * XP2 + r);
            float4 x1 = *(float4*)(xs + (u0+1) * XP2 + r);
            a00 += q0.x*x0.x + q0.y*x0.y + q0.z*x0.z + q0.w*x0.w;
            a01 += q0.x*x1.x + q0.y*x1.y + q0.z*x1.z + q0.w*x1.w;
            a10 += q1.x*x0.x + q1.y*x0.y + q1.z*x0.z + q1.w*x0.w;
            a11 += q1.x*x1.x + q1.y*x1.y + q1.z*x1.z + q1.w*x1.w;
        }
        ss[t0 * LL + u0]       = a00 * SCALE_INV;
        ss[t0 * LL + u0 + 1]   = a01 * SCALE_INV;
        ss[(t0+1) * LL + u0]   = a10 * SCALE_INV;
        ss[(t0+1) * LL + u0+1] = a11 * SCALE_INV;
    }
    __syncthreads();

    if (tid < LL) {
        float m = -1e30f;
        for (int u = 0; u < LL; u++) m = fmaxf(m, ss[tid * LL + u]);
        float s = 0.f;
        for (int u = 0; u < LL; u++) {
            float ev = __expf(ss[tid * LL + u] - m);
            ss[tid * LL + u] = ev; s += ev;
        }
        float inv = 1.f / s;
        for (int u = 0; u < LL; u++) ss[tid * LL + u] *= inv;
    }
    __syncthreads();

    for (int i = tid; i < LL * VV; i += 256) {
        int t = i >> 4, v = i & 15;
        float acc = 0.f;
        for (int u = 0; u < LL; u++) acc += ss[t * LL + u] * xv[u * VV + v];
        P_WORD[(tok0 + t) * RR + h * VV + v] = acc;
    }
}

// =====================================================================
// diag scores: qi(fp16)[20,256] . word(fp32)[20,256]^T
// =====================================================================
__global__ void __launch_bounds__(128) k_diag(int hg)
{
    __shared__ float qs[LL * 260];
    __shared__ float xs[LL * 260];
    const int hl = blockIdx.x, h = hg + hl;
    const int seq = blockIdx.y, tok0 = seq * LL;
    const int tid = threadIdx.x;

    for (int i = tid; i < LL * RR; i += 128) {
        int t = i >> 8, r = i & 255;
        qs[t * 260 + r] = __half2float(H_SCR[((size_t)hl * NTOKP + tok0 + t) * 256 + r]);
        xs[t * 260 + r] = P_WORD[(tok0 + t) * RR + r];
    }
    __syncthreads();

    if (tid < 100) {
        const int t0 = (tid / 10) * 2, u0 = (tid % 10) * 2;
        float a00=0,a01=0,a10=0,a11=0;
        for (int r = 0; r < RR; r += 4) {
            float4 q0 = *(float4*)(qs + t0 * 260 + r);
            float4 q1 = *(float4*)(qs + (t0+1) * 260 + r);
            float4 x0 = *(float4*)(xs + u0 * 260 + r);
            float4 x1 = *(float4*)(xs + (u0+1) * 260 + r);
            a00 += q0.x*x0.x + q0.y*x0.y + q0.z*x0.z + q0.w*x0.w;
            a01 += q0.x*x1.x + q0.y*x1.y + q0.z*x1.z + q0.w*x1.w;
            a10 += q1.x*x0.x + q1.y*x0.y + q1.z*x0.z + q1.w*x0.w;
            a11 += q1.x*x1.x + q1.y*x1.y + q1.z*x1.z + q1.w*x1.w;
        }
        float* D = P_SDIAG + (seq * HH + h) * (LL * LL);
        D[t0 * LL + u0]       = a00;
        D[t0 * LL + u0 + 1]   = a01;
        D[(t0+1) * LL + u0]   = a10;
        D[(t0+1) * LL + u0+1] = a11;
    }
}

// =====================================================================
// per-pair: assemble scores + softmax + A@V + keyW + pool
// =====================================================================
#define VSTR 260
#define SMEM_PAIR2 ((TT*44 + 44*VSTR + 44*VV + 16*QQ + QQ + QQ + 48 + 48) * 4)

__global__ void __launch_bounds__(256) k_pair2(
    const float* __restrict__ keyW, const float* __restrict__ keyb,
    const float* __restrict__ query)
{
    extern __shared__ float sm[];
    float* S    = sm;
    float* Vals = S + TT * 44;
    float* Vh   = Vals + 44 * VSTR;
    float* kwst = Vh + 44 * VV;
    float* kb   = kwst + 16 * QQ;
    float* qv   = kb + QQ;
    float* logits = qv + QQ;
    float* a2   = logits + 48;

    const int p = blockIdx.x;
    const int b = p / (CDD * HIS);
    const int rem = p - b * (CDD * HIS);
    const int c = rem / HIS;
    const int h2 = rem - c * HIS;
    const int cddSeq = b * CDD + c;
    const int hisSeq = 20 + b * HIS + h2;
    const int cddTok0 = cddSeq * LL;
    const int hisTok0 = hisSeq * LL;
    const int tid = threadIdx.x;

    for (int i = tid; i < QQ; i += 256) { kb[i] = keyb[i]; qv[i] = query[i]; }
    for (int i = tid; i < 3 * VSTR; i += 256) Vals[TT * VSTR + i] = 0.f;
    __syncthreads();

    for (int h = 0; h < HH; h++) {
        for (int i = tid; i < TT * TT; i += 256) {
            int t = i / TT, u = i - t * TT;
            float v;
            if (t < LL) {
                if (u < LL)
                    v = P_SDIAG[(cddSeq * HH + h) * 400 + t * LL + u];
                else if (u == LL)
                    v = P_AUX[(cddTok0 + t) * 32 + 2*h + 1];
                else
                    v = __half2float(P_C1[(size_t)(b * HH + h) * 100000
                                          + (c * LL + t) * 1000 + h2 * LL + (u - 21)]);
            } else if (t == LL) {
                if (u < LL)       v = P_AUX[(cddTok0 + u) * 32 + 2*h];
                else if (u == LL) v = P_AUX[NTOKW * 32 + 2*h];
                else              v = P_AUX[(hisTok0 + u - 21) * 32 + 2*h];
            } else {
                int tt = t - 21;
                if (u < LL)
                    v = __half2float(P_C2[(size_t)(b * HH + h) * 100000
                                          + (h2 * LL + tt) * 100 + c * LL + u]);
                else if (u == LL)
                    v = P_AUX[(hisTok0 + tt) * 32 + 2*h + 1];
                else
                    v = P_SDIAG[(hisSeq * HH + h) * 400 + tt * LL + (u - 21)];
            }
            S[t * 44 + u] = v * SCALE_INV;
        }
        for (int i = tid; i < TT * VV; i += 256) {
            int t = i >> 4, v = i & 15;
            int tok = (t < LL) ? (cddTok0 + t) : (t == LL) ? NTOKW : (hisTok0 + t - 21);
            Vh[t * VV + v] = P_V[tok * RR + h * VV + v];
        }
        __syncthreads();

        if (tid < TT) {
            float m = -1e30f;
            for (int u = 0; u < TT; u++) m = fmaxf(m, S[tid * 44 + u]);
            float s = 0.f;
            for (int u = 0; u < TT; u++) {
                float ev = __expf(S[tid * 44 + u] - m);
                S[tid * 44 + u] = ev; s += ev;
            }
            float inv = 1.f / s;
            for (int u = 0; u < TT; u++) S[tid * 44 + u] *= inv;
        }
        __syncthreads();

        for (int i = tid; i < TT * VV; i += 256) {
            int t = i >> 4, v = i & 15;
            float acc = 0.f;
            for (int u = 0; u < TT; u++) acc += S[t * 44 + u] * Vh[u * VV + v];
            Vals[t * VSTR + h * VV + v] = acc;
        }
        __syncthreads();
    }

    const int vti = tid / 20, vqi = tid % 20;
    const bool vact = (tid < 220);
    float kacc[4][10];
    if (vact)
#pragma unroll
        for (int a = 0; a < 4; a++)
#pragma unroll
            for (int j = 0; j < 10; j++) kacc[a][j] = 0.f;

    for (int r0 = 0; r0 < RR; r0 += 16) {
        __syncthreads();
        for (int i = tid; i < 16 * QQ; i += 256) {
            int rr = i / QQ, q_ = i - rr * QQ;
            kwst[rr * QQ + q_] = keyW[(r0 + rr) * QQ + q_];
        }
        __syncthreads();
        if (vact) {
            const int t0 = vti * 4, q0 = vqi * 10;
            for (int rr = 0; rr < 16; rr++) {
                float vv[4];
#pragma unroll
                for (int a = 0; a < 4; a++) vv[a] = Vals[(t0 + a) * VSTR + r0 + rr];
#pragma unroll
                for (int j = 0; j < 10; j++) {
                    float w = kwst[rr * QQ + q0 + j];
#pragma unroll
                    for (int a = 0; a < 4; a++) kacc[a][j] += vv[a] * w;
                }
            }
        }
    }
    __syncthreads();

    if (vact) {
        const int q0 = vqi * 10;
#pragma unroll
        for (int a = 0; a < 4; a++) {
            float part = 0.f;
#pragma unroll
            for (int j = 0; j < 10; j++) {
                float kv = tanhf(kacc[a][j] + kb[q0 + j]);
                part += kv * qv[q0 + j];
            }
            S[tid * 4 + a] = part;
        }
    }
    __syncthreads();

    if (tid < TT) {
        int t0i = tid >> 2, sub = tid & 3;
        float s = 0.f;
        for (int qi = 0; qi < 20; qi++) s += S[(t0i * 20 + qi) * 4 + sub];
        logits[tid] = s * SCALE_INV;
    }
    __syncthreads();
    if (tid == 0) {
        float m = -1e30f;
        for (int t = 0; t < TT; t++) m = fmaxf(m, logits[t]);
        float s = 0.f;
        for (int t = 0; t < TT; t++) { float ev = __expf(logits[t] - m); a2[t] = ev; s += ev; }
        float inv = 1.f / s;
        for (int t = 0; t < TT; t++) a2[t] *= inv;
    }
    __syncthreads();

    if (tid < RR) {
        float acc = 0.f;
        for (int t = 0; t < TT; t++) acc += a2[t] * Vals[t * VSTR + tid];
        P_REP[p * RR + tid] = acc;
    }
}

// =====================================================================
// final
// =====================================================================
__global__ void __launch_bounds__(256) k_final(
    const float* __restrict__ ltr_w, const float* __restrict__ ltr_b,
    float* __restrict__ out)
{
    __shared__ float red[256];
    __shared__ float sc[CDD];
    const int b = blockIdx.x;
    const int tid = threadIdx.x;

    for (int c = 0; c < CDD; c++) {
        float s = 0.f;
        const int base = ((b * CDD + c) * HIS) * RR + tid;
        for (int hh = 0; hh < HIS; hh++) s += P_REP[base + hh * RR];
        red[tid] = s * (1.f / HIS) * ltr_w[tid];
        __syncthreads();
        for (int st = 128; st > 0; st >>= 1) {
            if (tid < st) red[tid] += red[tid + st];
            __syncthreads();
        }
        if (tid == 0) sc[c] = red[0] + ltr_b[0];
        __syncthreads();
    }
    if (tid == 0) {
        float m = -1e30f;
        for (int c = 0; c < CDD; c++) m = fmaxf(m, sc[c]);
        float s = 0.f;
        for (int c = 0; c < CDD; c++) s += __expf(sc[c] - m);
        float lse = m + logf(s);
        for (int c = 0; c < CDD; c++) out[b * CDD + c] = sc[c] - lse;
    }
}

// =====================================================================
// launch
// =====================================================================
extern "C" void kernel_launch(void* const* d_in, const int* in_sizes, int n_in,
                              void* d_out, int out_size)
{
    const int*   cand  = (const int*)d_in[0];
    const int*   clik  = (const int*)d_in[1];
    const float* emb   = (const float*)d_in[2];
    const float* Wq_w  = (const float*)d_in[3];
    const float* Wv_w  = (const float*)d_in[4];
    const float* Wq_i  = (const float*)d_in[5];
    const float* Wv_i  = (const float*)d_in[6];
    const float* keyW  = (const float*)d_in[7];
    const float* keyb  = (const float*)d_in[8];
    const float* query = (const float*)d_in[9];
    const float* ltr_w = (const float*)d_in[10];
    const float* ltr_b = (const float*)d_in[11];
    float* out = (float*)d_out;

    cudaFuncSetAttribute(k_word2, cudaFuncAttributeMaxDynamicSharedMemorySize, SMEM_WORD2);
    cudaFuncSetAttribute(k_pair2, cudaFuncAttributeMaxDynamicSharedMemorySize, SMEM_PAIR2);

    k_tok<<<(NTOKW + 255) / 256, 256>>>(cand, clik);
    k_w1aux<<<HH, 256>>>(Wq_i);
    k_embh16<<<(NTOKW * 320 + 255) / 256, 256>>>(emb);
    k_gemm_xv<<<dim3(4, 35), 256>>>(emb, Wv_w);
    k_wT<<<(HH * 300 * 320 + 255) / 256, 256>>>(Wq_w, 300, 300, 320);

    // word phase: q via HMMA fp16 GEMM, 4-head groups
    for (int g = 0; g < NGRP; g++) {
        k_mma<<<dim3(5, 35, HG), 256>>>(0, g * HG);
        k_word2<<<dim3(HG, 220), 256, SMEM_WORD2>>>(g * HG);
    }

    k_wordh16<<<(NTOKP * RR + 255) / 256, 256>>>();
    k_gemm_vi<<<dim3(5, 35), 256>>>(Wv_i);
    k_wT<<<(HH * 256 * 256 + 255) / 256, 256>>>(Wq_i, 256, 256, 256);

    // itrs phase: qi + cross scores via HMMA, 4-head groups
    for (int g = 0; g < NGRP; g++) {
        k_mma<<<dim3(4, 35, HG), 256>>>(1, g * HG);
        k_diag<<<dim3(HG, 220), 128>>>(g * HG);
        k_mma<<<dim3(16, 1, BB * HG), 256>>>(2, g * HG);  // C1
        k_mma<<<dim3(2, 8, BB * HG), 256>>>(3, g * HG);   // C2
    }

    k_pair2<<<NPAIR, 256, SMEM_PAIR2>>>(keyW, keyb, query);
    k_final<<<BB, 256>>>(ltr_w, ltr_b, out);
}